// round 15
// baseline (speedup 1.0000x reference)
#include <cuda_runtime.h>
#include <math.h>
#include <stdint.h>

// Problem constants
#define BATCH 2
#define SEQ   2048
#define DIM   1024
#define HEADS 16
#define DKV   64
#define MROWS (BATCH*SEQ)                          // 4096
#define OUT_ELEMS   ((size_t)MROWS*DIM)            // 4194304
#define PB_ELEMS    ((size_t)HEADS*SEQ*SEQ)        // 67108864
#define BIAS_TBL_N  (HEADS*4095)                   // 65520

// Scratch (device globals, no runtime allocation)
__device__ float g_q[MROWS*DIM];
__device__ float g_k[MROWS*DIM];
__device__ float g_v[MROWS*DIM];
__device__ float g_attn[MROWS*DIM];
__device__ float g_bias_tbl[BIAS_TBL_N];

// ---------------------------------------------------------------------------
// TF32 / cp.async helpers
// ---------------------------------------------------------------------------
__device__ __forceinline__ uint32_t f2tf(float f) {       // RNA round (P/V/1-term)
    uint32_t u;
    asm("cvt.rna.tf32.f32 %0, %1;" : "=r"(u) : "f"(f));
    return u;
}
// 2-op truncating split (verified R14): hi = top-19-bit truncation, lo = f-hi.
__device__ __forceinline__ float2 split2t(float f) {
    float hf = __uint_as_float(__float_as_uint(f) & 0xffffe000u);
    return make_float2(hf, f - hf);
}

__device__ __forceinline__ void mma8(float& d0, float& d1, float& d2, float& d3,
                                     uint32_t a0, uint32_t a1, uint32_t a2, uint32_t a3,
                                     uint32_t b0, uint32_t b1)
{
    asm volatile("mma.sync.aligned.m16n8k8.row.col.f32.tf32.tf32.f32 "
                 "{%0,%1,%2,%3}, {%4,%5,%6,%7}, {%8,%9}, {%0,%1,%2,%3};"
                 : "+f"(d0), "+f"(d1), "+f"(d2), "+f"(d3)
                 : "r"(a0), "r"(a1), "r"(a2), "r"(a3), "r"(b0), "r"(b1));
}

__device__ __forceinline__ void cp16(uint32_t dst, const void* src) {
    asm volatile("cp.async.cg.shared.global [%0], [%1], 16;" :: "r"(dst), "l"(src));
}
__device__ __forceinline__ void cp4(uint32_t dst, const void* src) {
    asm volatile("cp.async.ca.shared.global [%0], [%1], 4;" :: "r"(dst), "l"(src));
}
// volatile shared load (prevents LICM hoisting of loop-invariant Q loads)
__device__ __forceinline__ float lds32v(uint32_t addr) {
    float v;
    asm volatile("ld.shared.f32 %0, [%1];" : "=f"(v) : "r"(addr));
    return v;
}

// ---------------------------------------------------------------------------
// Relative-position bias table: bias[h][rel + 2047], rel = k - q
// ---------------------------------------------------------------------------
__global__ void bias_table_kernel(const float* __restrict__ rel_table,
                                  float* __restrict__ bias)
{
    int i = blockIdx.x * blockDim.x + threadIdx.x;
    if (i >= BIAS_TBL_N) return;
    int h   = i / 4095;
    int rel = (i % 4095) - 2047;       // rel = k - q
    int n   = -rel;                    // q - k
    int ret = 0;
    if (n < 0) { ret = 16; n = -n; }
    int val;
    if (n < 8) {
        val = n;
    } else {
        float t = (logf((float)n / 8.0f) / 2.772588722239781f) * 8.0f;
        int it = (int)t;
        if (t - (float)it > 0.99995f) it += 1;
        val = 8 + it;
        if (val > 15) val = 15;
    }
    bias[i] = rel_table[(val + ret) * HEADS + h];
}

// ---------------------------------------------------------------------------
// Fused QKV projection GEMM, cp.async double-buffered, BK=64.
// z==0: Q (3-term, raw store)  z==1: K (3-term, raw store)
// z==2: V (1-term, tf32-rounded store)
// BM=128 BN=64 BK=64, 256 thr.
// ---------------------------------------------------------------------------
#define QKV_AR_STR 68   // floats per A row (128 rows, raw)
#define QKV_BR_STR 68   // floats per B row (64 rows, raw)
#define QKV_A_SZ (128*QKV_AR_STR)    // 8704
#define QKV_B_SZ (64*QKV_BR_STR)     // 4352
#define QKV_SMEM_BYTES ((2*QKV_A_SZ + 2*QKV_B_SZ) * 4)   // 104448

__global__ __launch_bounds__(256, 2) void gemm_qkv(const float* __restrict__ A,
                                                   const float* __restrict__ Wq,
                                                   const float* __restrict__ Wk,
                                                   const float* __restrict__ Wv,
                                                   float* __restrict__ Cq,
                                                   float* __restrict__ Ck,
                                                   float* __restrict__ Cv,
                                                   int M, int N, int K)
{
    const int z = blockIdx.z;
    const float* B = (z == 0) ? Wq : (z == 1 ? Wk : Wv);
    float*       C = (z == 0) ? Cq : (z == 1 ? Ck : Cv);

    extern __shared__ float smg[];
    float* Ar = smg;                     // [2][128][QKV_AR_STR]
    float* Br = smg + 2 * QKV_A_SZ;      // [2][64][QKV_BR_STR]
    const uint32_t su = (uint32_t)__cvta_generic_to_shared(smg);

    const int tid  = threadIdx.x;
    const int lane = tid & 31;
    const int warp = tid >> 5;
    const int wm   = warp >> 1;          // 0..3
    const int wn   = warp & 1;           // 0..1
    const int l4   = lane >> 2;          // 0..7
    const int lc   = lane & 3;           // 0..3
    const int m0   = blockIdx.y * 128;
    const int n0   = blockIdx.x * 64;

    float acc[2][4][4];
#pragma unroll
    for (int mt = 0; mt < 2; mt++)
#pragma unroll
        for (int nt = 0; nt < 4; nt++)
#pragma unroll
            for (int j = 0; j < 4; j++) acc[mt][nt][j] = 0.f;

    // staging: A 128x64 (32 floats/thread), B 64x64 (16 floats/thread)
    const int ar = tid >> 1, ac = (tid & 1) * 32;
    const int br = tid >> 2, bc = (tid & 3) * 16;
    const float* Ap = A + (size_t)(m0 + ar) * K + ac;
    const float* Bp = B + (size_t)br * N + n0 + bc;

    auto stage = [&](int kt, int buf) {
        const float* Aq = Ap + kt * 64;
        const float* Bq = Bp + (size_t)kt * 64 * N;
        uint32_t ad = su + (uint32_t)(buf * QKV_A_SZ + ar * QKV_AR_STR + ac) * 4;
        uint32_t bd = su + (uint32_t)(2 * QKV_A_SZ + buf * QKV_B_SZ + br * QKV_BR_STR + bc) * 4;
#pragma unroll
        for (int j = 0; j < 8; j++) cp16(ad + 16 * j, Aq + 4 * j);
#pragma unroll
        for (int j = 0; j < 4; j++) cp16(bd + 16 * j, Bq + 4 * j);
        asm volatile("cp.async.commit_group;");
    };

    stage(0, 0);
    const int NT = K / 64;   // 16

    for (int kt = 0; kt < NT; kt++) {
        const int cur = kt & 1;
        __syncthreads();
        if (kt + 1 < NT) {
            stage(kt + 1, cur ^ 1);
            asm volatile("cp.async.wait_group 1;");
        } else {
            asm volatile("cp.async.wait_group 0;");
        }
        __syncthreads();

        const float* Ac = Ar + cur * QKV_A_SZ;
        const float* Bc = Br + cur * QKV_B_SZ;

        if (z < 2) {
            // ---- 3-term (split2t) path for Q/K ----
#pragma unroll
            for (int s = 0; s < 8; s++) {
                const int kk = s * 8 + lc;
                uint32_t ah[2][4], al[2][4];
#pragma unroll
                for (int mt = 0; mt < 2; mt++) {
                    int row = wm * 32 + mt * 16 + l4;
                    float2 t;
                    t = split2t(Ac[(row)     * QKV_AR_STR + kk]);     ah[mt][0] = __float_as_uint(t.x); al[mt][0] = __float_as_uint(t.y);
                    t = split2t(Ac[(row + 8) * QKV_AR_STR + kk]);     ah[mt][1] = __float_as_uint(t.x); al[mt][1] = __float_as_uint(t.y);
                    t = split2t(Ac[(row)     * QKV_AR_STR + kk + 4]); ah[mt][2] = __float_as_uint(t.x); al[mt][2] = __float_as_uint(t.y);
                    t = split2t(Ac[(row + 8) * QKV_AR_STR + kk + 4]); ah[mt][3] = __float_as_uint(t.x); al[mt][3] = __float_as_uint(t.y);
                }
#pragma unroll
                for (int nt = 0; nt < 4; nt++) {
                    int col = wn * 32 + nt * 8 + l4;
                    float2 b0 = split2t(Bc[(kk)     * QKV_BR_STR + col]);
                    float2 b1 = split2t(Bc[(kk + 4) * QKV_BR_STR + col]);
                    uint32_t bh0 = __float_as_uint(b0.x), bl0 = __float_as_uint(b0.y);
                    uint32_t bh1 = __float_as_uint(b1.x), bl1 = __float_as_uint(b1.y);
#pragma unroll
                    for (int mt = 0; mt < 2; mt++) {
                        mma8(acc[mt][nt][0], acc[mt][nt][1], acc[mt][nt][2], acc[mt][nt][3],
                             ah[mt][0], ah[mt][1], ah[mt][2], ah[mt][3], bh0, bh1);
                        mma8(acc[mt][nt][0], acc[mt][nt][1], acc[mt][nt][2], acc[mt][nt][3],
                             ah[mt][0], ah[mt][1], ah[mt][2], ah[mt][3], bl0, bl1);
                        mma8(acc[mt][nt][0], acc[mt][nt][1], acc[mt][nt][2], acc[mt][nt][3],
                             al[mt][0], al[mt][1], al[mt][2], al[mt][3], bh0, bh1);
                    }
                }
            }
        } else {
            // ---- 1-term (RNA cvt) path for V ----
#pragma unroll
            for (int s = 0; s < 8; s++) {
                const int kk = s * 8 + lc;
                uint32_t a[2][4];
#pragma unroll
                for (int mt = 0; mt < 2; mt++) {
                    int row = wm * 32 + mt * 16 + l4;
                    a[mt][0] = f2tf(Ac[(row)     * QKV_AR_STR + kk]);
                    a[mt][1] = f2tf(Ac[(row + 8) * QKV_AR_STR + kk]);
                    a[mt][2] = f2tf(Ac[(row)     * QKV_AR_STR + kk + 4]);
                    a[mt][3] = f2tf(Ac[(row + 8) * QKV_AR_STR + kk + 4]);
                }
#pragma unroll
                for (int nt = 0; nt < 4; nt++) {
                    int col = wn * 32 + nt * 8 + l4;
                    uint32_t b0 = f2tf(Bc[(kk)     * QKV_BR_STR + col]);
                    uint32_t b1 = f2tf(Bc[(kk + 4) * QKV_BR_STR + col]);
#pragma unroll
                    for (int mt = 0; mt < 2; mt++) {
                        mma8(acc[mt][nt][0], acc[mt][nt][1], acc[mt][nt][2], acc[mt][nt][3],
                             a[mt][0], a[mt][1], a[mt][2], a[mt][3], b0, b1);
                    }
                }
            }
        }
    }

#pragma unroll
    for (int mt = 0; mt < 2; mt++) {
#pragma unroll
        for (int nt = 0; nt < 4; nt++) {
            int row = m0 + wm * 32 + mt * 16 + l4;
            int col = n0 + wn * 32 + nt * 8 + 2 * lc;
            float v0 = acc[mt][nt][0], v1 = acc[mt][nt][1];
            float v2 = acc[mt][nt][2], v3 = acc[mt][nt][3];
            if (z == 2) {   // V: pre-round to tf32 for the attention PV stage
                v0 = __uint_as_float(f2tf(v0)); v1 = __uint_as_float(f2tf(v1));
                v2 = __uint_as_float(f2tf(v2)); v3 = __uint_as_float(f2tf(v3));
            }
            *(float2*)&C[(size_t)(row)     * N + col] = make_float2(v0, v1);
            *(float2*)&C[(size_t)(row + 8) * N + col] = make_float2(v2, v3);
        }
    }
}

// ---------------------------------------------------------------------------
// Plain TF32 GEMM (1 MMA per k8), cp.async double-buffered, BK=32:
// O-projection; gridDim.z==2 launches also emit the position_bias broadcast
// on z==1 CTAs. (Verified R10 body.)
// ---------------------------------------------------------------------------
#define AR_STR 36
#define BR_STR 68
#define G1_A_SZ (128*AR_STR)
#define G1_B_SZ (32*BR_STR)
#define GEMM1_SMEM_BYTES ((2*G1_A_SZ + 2*G1_B_SZ) * 4)   // 54272

__global__ __launch_bounds__(256, 2) void gemm_tf32_1t(const float* __restrict__ A,
                                                       const float* __restrict__ B,
                                                       float* __restrict__ C,
                                                       const float* __restrict__ bias_tbl,
                                                       float* __restrict__ pb,
                                                       int M, int N, int K)
{
    if (blockIdx.z == 1) {
        // position_bias broadcast: 512 CTAs x 256 thr x 128 iters x float4
        int cta = blockIdx.y * gridDim.x + blockIdx.x;       // 0..511
        size_t base = (size_t)cta * 131072 + threadIdx.x * 4;
#pragma unroll 4
        for (int it = 0; it < 128; it++) {
            size_t i = base + (size_t)it * 1024;
            int k = (int)(i & 2047);
            int q = (int)((i >> 11) & 2047);
            int h = (int)(i >> 22);
            const float* src = bias_tbl + h * 4095 + 2047 - q + k;
            *(float4*)(pb + i) = make_float4(src[0], src[1], src[2], src[3]);
        }
        return;
    }

    extern __shared__ float smg[];
    float* Ar = smg;                   // [2][128][AR_STR]
    float* Br = smg + 2 * G1_A_SZ;     // [2][32][BR_STR]
    const uint32_t su = (uint32_t)__cvta_generic_to_shared(smg);

    const int tid  = threadIdx.x;
    const int lane = tid & 31;
    const int warp = tid >> 5;
    const int wm   = warp >> 1;
    const int wn   = warp & 1;
    const int l4   = lane >> 2;
    const int lc   = lane & 3;
    const int m0   = blockIdx.y * 128;
    const int n0   = blockIdx.x * 64;

    float acc[2][4][4];
#pragma unroll
    for (int mt = 0; mt < 2; mt++)
#pragma unroll
        for (int nt = 0; nt < 4; nt++)
#pragma unroll
            for (int j = 0; j < 4; j++) acc[mt][nt][j] = 0.f;

    const int ar = tid >> 1, ac = (tid & 1) * 16;
    const int br = tid >> 3, bc = (tid & 7) * 8;
    const float* Ap = A + (size_t)(m0 + ar) * K + ac;
    const float* Bp = B + (size_t)br * N + n0 + bc;

    auto stage = [&](int kt, int buf) {
        const float* Aq = Ap + kt * 32;
        const float* Bq = Bp + (size_t)kt * 32 * N;
        uint32_t ad = su + (uint32_t)(buf * G1_A_SZ + ar * AR_STR + ac) * 4;
        uint32_t bd = su + (uint32_t)(2 * G1_A_SZ + buf * G1_B_SZ + br * BR_STR + bc) * 4;
#pragma unroll
        for (int j = 0; j < 4; j++) cp16(ad + 16 * j, Aq + 4 * j);
#pragma unroll
        for (int j = 0; j < 2; j++) cp16(bd + 16 * j, Bq + 4 * j);
        asm volatile("cp.async.commit_group;");
    };

    stage(0, 0);
    const int NT = K / 32;

    for (int kt = 0; kt < NT; kt++) {
        const int cur = kt & 1;
        __syncthreads();
        if (kt + 1 < NT) {
            stage(kt + 1, cur ^ 1);
            asm volatile("cp.async.wait_group 1;");
        } else {
            asm volatile("cp.async.wait_group 0;");
        }
        __syncthreads();

        const float* Ac = Ar + cur * G1_A_SZ;
        const float* Bc = Br + cur * G1_B_SZ;

#pragma unroll
        for (int s = 0; s < 4; s++) {
            const int kk = s * 8 + lc;
            uint32_t a[2][4];
#pragma unroll
            for (int mt = 0; mt < 2; mt++) {
                int row = wm * 32 + mt * 16 + l4;
                a[mt][0] = f2tf(Ac[(row)     * AR_STR + kk]);
                a[mt][1] = f2tf(Ac[(row + 8) * AR_STR + kk]);
                a[mt][2] = f2tf(Ac[(row)     * AR_STR + kk + 4]);
                a[mt][3] = f2tf(Ac[(row + 8) * AR_STR + kk + 4]);
            }
#pragma unroll
            for (int nt = 0; nt < 4; nt++) {
                int col = wn * 32 + nt * 8 + l4;
                uint32_t b0 = f2tf(Bc[(kk)     * BR_STR + col]);
                uint32_t b1 = f2tf(Bc[(kk + 4) * BR_STR + col]);
#pragma unroll
                for (int mt = 0; mt < 2; mt++) {
                    mma8(acc[mt][nt][0], acc[mt][nt][1], acc[mt][nt][2], acc[mt][nt][3],
                         a[mt][0], a[mt][1], a[mt][2], a[mt][3], b0, b1);
                }
            }
        }
    }

#pragma unroll
    for (int mt = 0; mt < 2; mt++) {
#pragma unroll
        for (int nt = 0; nt < 4; nt++) {
            int row = m0 + wm * 32 + mt * 16 + l4;
            int col = n0 + wn * 32 + nt * 8 + 2 * lc;
            *(float2*)&C[(size_t)(row)     * N + col] = make_float2(acc[mt][nt][0], acc[mt][nt][1]);
            *(float2*)&C[(size_t)(row + 8) * N + col] = make_float2(acc[mt][nt][2], acc[mt][nt][3]);
        }
    }
}

// ---------------------------------------------------------------------------
// Flash attention (verified R14 body, unchanged). cp.async double-buffered,
// 2 CTAs/SM, 256 thr, Q-tile 128, K-tile 64, 2-op splits, shuffle P->A frags.
// ---------------------------------------------------------------------------
#define NTILE   (SEQ/64)                 // 32
#define SS_STR  68                        // Qs: [128][68] raw Q (persistent)
#define KR_STR  68                        // Kr: [2][64][68] raw K
#define VR_STR  72                        // Vr: [2][64][72] tf32 V
#define KR_OFF  (128*SS_STR)              // 8704
#define VR_OFF  (KR_OFF + 2*64*KR_STR)    // 17408
#define BW_OFF  (VR_OFF + 2*64*VR_STR)    // 26624
#define MS_OFF  (BW_OFF + 2*192)          // 27008
#define ATTN_SMEM_FLOATS (MS_OFF + 2*64)  // 27136
#define ATTN_SMEM_BYTES  (ATTN_SMEM_FLOATS * 4)   // 108544

__global__ __launch_bounds__(256, 2) void attn_tf32(const float* __restrict__ Q,
                                                    const float* __restrict__ K,
                                                    const float* __restrict__ V,
                                                    const float* __restrict__ mask,
                                                    const float* __restrict__ bias,
                                                    float* __restrict__ O)
{
    extern __shared__ float smf[];
    float* Qs = smf;                    // [128][SS_STR] raw Q, persistent
    float* Kr = smf + KR_OFF;           // [2][64][KR_STR]
    float* Vr = smf + VR_OFF;           // [2][64][VR_STR]
    float* bw = smf + BW_OFF;           // [2][192]
    float* ms = smf + MS_OFF;           // [2][64]
    const uint32_t smem_u = (uint32_t)__cvta_generic_to_shared(smf);

    const int tid  = threadIdx.x;
    const int lane = tid & 31;
    const int warp = tid >> 5;
    const int l4   = lane >> 2;
    const int lc   = lane & 3;
    const int b    = blockIdx.z;
    const int h    = blockIdx.y;
    const int q0   = blockIdx.x * 128;
    const int r0   = warp * 16 + l4;
    const int relbase = h * 4095 + 2047 - q0 - 127;   // + k0 + t

    const int sr = tid >> 2;
    const int sc = (tid & 3) * 16;
    const float* Kst = K + ((size_t)(b * SEQ + sr)) * DIM + h * DKV + sc;
    const float* Vst = V + ((size_t)(b * SEQ + sr)) * DIM + h * DKV + sc;

    auto stage = [&](int k0, int buf) {
        const float* Kb = Kst + (size_t)k0 * DIM;
        const float* Vb = Vst + (size_t)k0 * DIM;
        uint32_t kd = smem_u + (uint32_t)(KR_OFF + buf * 64 * KR_STR + sr * KR_STR + sc) * 4;
        uint32_t vd = smem_u + (uint32_t)(VR_OFF + buf * 64 * VR_STR + sr * VR_STR + sc) * 4;
#pragma unroll
        for (int j = 0; j < 4; j++) {
            cp16(kd + 16 * j, Kb + 4 * j);
            cp16(vd + 16 * j, Vb + 4 * j);
        }
        if (tid < 191) {
            cp4(smem_u + (uint32_t)(BW_OFF + buf * 192 + tid) * 4,
                bias + relbase + k0 + tid);
        } else if (tid >= 192) {
            cp4(smem_u + (uint32_t)(MS_OFF + buf * 64 + tid - 192) * 4,
                mask + b * SEQ + k0 + tid - 192);
        }
        asm volatile("cp.async.commit_group;");
    };

    stage(0, 0);

    {
        int r = tid >> 1, c0 = (tid & 1) * 32;
        const float* Qb = Q + ((size_t)(b * SEQ + q0 + r)) * DIM + h * DKV + c0;
#pragma unroll
        for (int j = 0; j < 8; j++)
            *(float4*)&Qs[r * SS_STR + c0 + 4 * j] = *(const float4*)(Qb + 4 * j);
    }
    __syncthreads();

    const uint32_t qrow0 = smem_u + (uint32_t)((r0)     * SS_STR) * 4;
    const uint32_t qrow8 = smem_u + (uint32_t)((r0 + 8) * SS_STR) * 4;

    float o[8][4];
#pragma unroll
    for (int dt = 0; dt < 8; dt++)
#pragma unroll
        for (int j = 0; j < 4; j++) o[dt][j] = 0.f;
    float mrow[2] = {-INFINITY, -INFINITY};
    float lrow[2] = {0.f, 0.f};

    for (int kt = 0; kt < NTILE; kt++) {
        const int cur = kt & 1;
        __syncthreads();
        if (kt + 1 < NTILE) {
            stage((kt + 1) * 64, cur ^ 1);
            asm volatile("cp.async.wait_group 1;");
        } else {
            asm volatile("cp.async.wait_group 0;");
        }
        __syncthreads();

        const float* Kc  = Kr + cur * 64 * KR_STR;
        const float* bwc = bw + cur * 192;
        const float* msc = ms + cur * 64;

        float sf[8][4];
#pragma unroll
        for (int nt = 0; nt < 8; nt++)
#pragma unroll
            for (int j = 0; j < 4; j++) sf[nt][j] = 0.f;

#pragma unroll
        for (int s = 0; s < 8; s++) {
            const int kk = s * 8 + lc;
            float2 qa0 = split2t(lds32v(qrow0 + (uint32_t)kk * 4));
            float2 qa1 = split2t(lds32v(qrow8 + (uint32_t)kk * 4));
            float2 qa2 = split2t(lds32v(qrow0 + (uint32_t)(kk + 4) * 4));
            float2 qa3 = split2t(lds32v(qrow8 + (uint32_t)(kk + 4) * 4));
            uint32_t qh0 = __float_as_uint(qa0.x), ql0 = __float_as_uint(qa0.y);
            uint32_t qh1 = __float_as_uint(qa1.x), ql1 = __float_as_uint(qa1.y);
            uint32_t qh2 = __float_as_uint(qa2.x), ql2 = __float_as_uint(qa2.y);
            uint32_t qh3 = __float_as_uint(qa3.x), ql3 = __float_as_uint(qa3.y);
#pragma unroll
            for (int nt = 0; nt < 8; nt++) {
                int key = nt * 8 + l4;
                float2 b0 = split2t(Kc[key * KR_STR + kk]);
                float2 b1 = split2t(Kc[key * KR_STR + kk + 4]);
                uint32_t bh0 = __float_as_uint(b0.x), bl0 = __float_as_uint(b0.y);
                uint32_t bh1 = __float_as_uint(b1.x), bl1 = __float_as_uint(b1.y);
                mma8(sf[nt][0], sf[nt][1], sf[nt][2], sf[nt][3],
                     qh0, qh1, qh2, qh3, bh0, bh1);
                mma8(sf[nt][0], sf[nt][1], sf[nt][2], sf[nt][3],
                     qh0, qh1, qh2, qh3, bl0, bl1);
                mma8(sf[nt][0], sf[nt][1], sf[nt][2], sf[nt][3],
                     ql0, ql1, ql2, ql3, bh0, bh1);
            }
        }

#pragma unroll
        for (int i = 0; i < 2; i++) {
            int qlcl = warp * 16 + l4 + 8 * i;
            float vmax = -INFINITY;
#pragma unroll
            for (int nt = 0; nt < 8; nt++) {
#pragma unroll
                for (int j = 0; j < 2; j++) {
                    int klcl = nt * 8 + 2 * lc + j;
                    float v = sf[nt][2 * i + j] + bwc[klcl - qlcl + 127] + msc[klcl];
                    sf[nt][2 * i + j] = v;
                    vmax = fmaxf(vmax, v);
                }
            }
            vmax = fmaxf(vmax, __shfl_xor_sync(0xffffffffu, vmax, 1));
            vmax = fmaxf(vmax, __shfl_xor_sync(0xffffffffu, vmax, 2));
            float mnew = fmaxf(mrow[i], vmax);
            float corr = __expf(mrow[i] - mnew);
            mrow[i] = mnew;
            float rsum = 0.f;
#pragma unroll
            for (int nt = 0; nt < 8; nt++) {
#pragma unroll
                for (int j = 0; j < 2; j++) {
                    float p = __expf(sf[nt][2 * i + j] - mnew);
                    sf[nt][2 * i + j] = p;
                    rsum += p;
                }
            }
            rsum += __shfl_xor_sync(0xffffffffu, rsum, 1);
            rsum += __shfl_xor_sync(0xffffffffu, rsum, 2);
            lrow[i] = lrow[i] * corr + rsum;
#pragma unroll
            for (int dt = 0; dt < 8; dt++) {
                o[dt][2 * i]     *= corr;
                o[dt][2 * i + 1] *= corr;
            }
        }

        const float* Vc = Vr + cur * 64 * VR_STR;
        const int qbase = lane & ~3;
        const int src1  = qbase | (lc >> 1);
        const int src2  = qbase | 2 | (lc >> 1);
        const bool odd  = (lc & 1);
#pragma unroll
        for (int s = 0; s < 8; s++) {
            const int kk = s * 8 + lc;
            float u0 = __shfl_sync(0xffffffffu, sf[s][0], src1);
            float v0 = __shfl_sync(0xffffffffu, sf[s][1], src1);
            float u1 = __shfl_sync(0xffffffffu, sf[s][2], src1);
            float v1 = __shfl_sync(0xffffffffu, sf[s][3], src1);
            float u2 = __shfl_sync(0xffffffffu, sf[s][0], src2);
            float v2 = __shfl_sync(0xffffffffu, sf[s][1], src2);
            float u3 = __shfl_sync(0xffffffffu, sf[s][2], src2);
            float v3 = __shfl_sync(0xffffffffu, sf[s][3], src2);
            uint32_t pa0 = f2tf(odd ? v0 : u0);
            uint32_t pa1 = f2tf(odd ? v1 : u1);
            uint32_t pa2 = f2tf(odd ? v2 : u2);
            uint32_t pa3 = f2tf(odd ? v3 : u3);
#pragma unroll
            for (int dt = 0; dt < 8; dt++) {
                int dc = dt * 8 + l4;
                uint32_t vb0 = __float_as_uint(Vc[(kk)     * VR_STR + dc]);
                uint32_t vb1 = __float_as_uint(Vc[(kk + 4) * VR_STR + dc]);
                mma8(o[dt][0], o[dt][1], o[dt][2], o[dt][3],
                     pa0, pa1, pa2, pa3, vb0, vb1);
            }
        }
    }

#pragma unroll
    for (int i = 0; i < 2; i++) {
        float inv = 1.0f / lrow[i];
        size_t base = ((size_t)(b * SEQ + q0 + warp * 16 + l4 + 8 * i)) * DIM + h * DKV;
#pragma unroll
        for (int dt = 0; dt < 8; dt++) {
            *(float2*)&O[base + dt * 8 + 2 * lc] =
                make_float2(o[dt][2 * i] * inv, o[dt][2 * i + 1] * inv);
        }
    }
}

// ---------------------------------------------------------------------------
// Launch
// ---------------------------------------------------------------------------
extern "C" void kernel_launch(void* const* d_in, const int* in_sizes, int n_in,
                              void* d_out, int out_size)
{
    const float* x         = (const float*)d_in[0];
    const float* Wq        = (const float*)d_in[1];
    const float* Wk        = (const float*)d_in[2];
    const float* Wv        = (const float*)d_in[3];
    const float* Wo        = (const float*)d_in[4];
    const float* rel_table = (const float*)d_in[5];
    const float* mask      = (const float*)d_in[6];
    float* out = (float*)d_out;

    float *pq, *pk, *pv, *pa, *pbias;
    cudaGetSymbolAddress((void**)&pq,    g_q);
    cudaGetSymbolAddress((void**)&pk,    g_k);
    cudaGetSymbolAddress((void**)&pv,    g_v);
    cudaGetSymbolAddress((void**)&pa,    g_attn);
    cudaGetSymbolAddress((void**)&pbias, g_bias_tbl);

    cudaFuncSetAttribute(gemm_qkv, cudaFuncAttributeMaxDynamicSharedMemorySize,
                         QKV_SMEM_BYTES);
    cudaFuncSetAttribute(gemm_tf32_1t, cudaFuncAttributeMaxDynamicSharedMemorySize,
                         GEMM1_SMEM_BYTES);
    cudaFuncSetAttribute(attn_tf32, cudaFuncAttributeMaxDynamicSharedMemorySize,
                         ATTN_SMEM_BYTES);

    // 1) bias table
    bias_table_kernel<<<(BIAS_TBL_N + 255) / 256, 256>>>(rel_table, pbias);

    // 2) fused Q,K,V projections (one launch; z=0,1 3-term; z=2 1-term V)
    dim3 qkvgrid(DIM / 64, MROWS / 128, 3);
    gemm_qkv<<<qkvgrid, 256, QKV_SMEM_BYTES>>>(x, Wq, Wk, Wv, pq, pk, pv,
                                               MROWS, DIM, DIM);

    // 3) flash attention (cp.async pipelined, 2 CTAs/SM, 2-op splits)
    dim3 agrid(SEQ / 128, HEADS, BATCH);
    attn_tf32<<<agrid, 256, ATTN_SMEM_BYTES>>>(pq, pk, pv, mask, pbias, pa);

    // 4) output projection (z=0) + position_bias broadcast (z=1), one launch
    dim3 ogrid(DIM / 64, MROWS / 128, 2);
    gemm_tf32_1t<<<ogrid, 256, GEMM1_SMEM_BYTES>>>(pa, Wo, out, pbias,
                                                   out + OUT_ELEMS, MROWS, DIM, DIM);
}

// round 16
// speedup vs baseline: 1.0408x; 1.0408x over previous
#include <cuda_runtime.h>
#include <math.h>
#include <stdint.h>

// Problem constants
#define BATCH 2
#define SEQ   2048
#define DIM   1024
#define HEADS 16
#define DKV   64
#define MROWS (BATCH*SEQ)                          // 4096
#define OUT_ELEMS   ((size_t)MROWS*DIM)            // 4194304
#define PB_ELEMS    ((size_t)HEADS*SEQ*SEQ)        // 67108864
#define BIAS_TBL_N  (HEADS*4095)                   // 65520

// Scratch (device globals, no runtime allocation)
__device__ float g_q[MROWS*DIM];
__device__ float g_k[MROWS*DIM];
__device__ float g_v[MROWS*DIM];
__device__ float g_attn[MROWS*DIM];
__device__ float g_bias_tbl[BIAS_TBL_N];

// ---------------------------------------------------------------------------
// TF32 / cp.async helpers
// ---------------------------------------------------------------------------
__device__ __forceinline__ uint32_t f2tf(float f) {       // RNA round (P/V/1-term)
    uint32_t u;
    asm("cvt.rna.tf32.f32 %0, %1;" : "=r"(u) : "f"(f));
    return u;
}
// 2-op truncating split (verified R14): hi = top-19-bit truncation, lo = f-hi.
__device__ __forceinline__ float2 split2t(float f) {
    float hf = __uint_as_float(__float_as_uint(f) & 0xffffe000u);
    return make_float2(hf, f - hf);
}

__device__ __forceinline__ void mma8(float& d0, float& d1, float& d2, float& d3,
                                     uint32_t a0, uint32_t a1, uint32_t a2, uint32_t a3,
                                     uint32_t b0, uint32_t b1)
{
    asm volatile("mma.sync.aligned.m16n8k8.row.col.f32.tf32.tf32.f32 "
                 "{%0,%1,%2,%3}, {%4,%5,%6,%7}, {%8,%9}, {%0,%1,%2,%3};"
                 : "+f"(d0), "+f"(d1), "+f"(d2), "+f"(d3)
                 : "r"(a0), "r"(a1), "r"(a2), "r"(a3), "r"(b0), "r"(b1));
}

__device__ __forceinline__ void cp16(uint32_t dst, const void* src) {
    asm volatile("cp.async.cg.shared.global [%0], [%1], 16;" :: "r"(dst), "l"(src));
}
__device__ __forceinline__ void cp4(uint32_t dst, const void* src) {
    asm volatile("cp.async.ca.shared.global [%0], [%1], 4;" :: "r"(dst), "l"(src));
}
// volatile shared load (prevents LICM hoisting of loop-invariant Q loads)
__device__ __forceinline__ float lds32v(uint32_t addr) {
    float v;
    asm volatile("ld.shared.f32 %0, [%1];" : "=f"(v) : "r"(addr));
    return v;
}

// ---------------------------------------------------------------------------
// Relative-position bias table: bias[h][rel + 2047], rel = k - q
// ---------------------------------------------------------------------------
__global__ void bias_table_kernel(const float* __restrict__ rel_table,
                                  float* __restrict__ bias)
{
    int i = blockIdx.x * blockDim.x + threadIdx.x;
    if (i >= BIAS_TBL_N) return;
    int h   = i / 4095;
    int rel = (i % 4095) - 2047;       // rel = k - q
    int n   = -rel;                    // q - k
    int ret = 0;
    if (n < 0) { ret = 16; n = -n; }
    int val;
    if (n < 8) {
        val = n;
    } else {
        float t = (logf((float)n / 8.0f) / 2.772588722239781f) * 8.0f;
        int it = (int)t;
        if (t - (float)it > 0.99995f) it += 1;
        val = 8 + it;
        if (val > 15) val = 15;
    }
    bias[i] = rel_table[(val + ret) * HEADS + h];
}

// ---------------------------------------------------------------------------
// 3xTF32 GEMM, cp.async double-buffered: C = A[M,K] @ B[K,N].
// BM=128 BN=64 BK=32, 256 thr, raw fp32 tiles in smem, 2-op split on the fly.
// z==0: Q   z==1: K   z==2: position_bias broadcast (DRAM-bound CTAs hidden
// under the long compute-bound QK waves).
// ---------------------------------------------------------------------------
#define AR_STR 36   // floats per A row (128 rows, raw)
#define BR_STR 68   // floats per B row (32 rows, raw)
#define G3_A_SZ (128*AR_STR)
#define G3_B_SZ (32*BR_STR)
#define GEMM_SMEM_BYTES ((2*G3_A_SZ + 2*G3_B_SZ) * 4)   // 54272

__global__ __launch_bounds__(256, 2) void gemm_tf32(const float* __restrict__ A,
                                                    const float* __restrict__ B0,
                                                    const float* __restrict__ B1,
                                                    float* __restrict__ C0,
                                                    float* __restrict__ C1,
                                                    const float* __restrict__ bias_tbl,
                                                    float* __restrict__ pb,
                                                    int M, int N, int K)
{
    if (blockIdx.z == 2) {
        // position_bias broadcast: 512 CTAs x 256 thr x 128 iters x float4
        int cta = blockIdx.y * gridDim.x + blockIdx.x;       // 0..511
        size_t base = (size_t)cta * 131072 + threadIdx.x * 4;
#pragma unroll 4
        for (int it = 0; it < 128; it++) {
            size_t i = base + (size_t)it * 1024;
            int k = (int)(i & 2047);
            int q = (int)((i >> 11) & 2047);
            int h = (int)(i >> 22);
            const float* src = bias_tbl + h * 4095 + 2047 - q + k;
            *(float4*)(pb + i) = make_float4(src[0], src[1], src[2], src[3]);
        }
        return;
    }

    const float* B = (blockIdx.z == 0) ? B0 : B1;
    float*       C = (blockIdx.z == 0) ? C0 : C1;

    extern __shared__ float smg[];
    float* Ar = smg;                   // [2][128][AR_STR]
    float* Br = smg + 2 * G3_A_SZ;     // [2][32][BR_STR]
    const uint32_t su = (uint32_t)__cvta_generic_to_shared(smg);

    const int tid  = threadIdx.x;
    const int lane = tid & 31;
    const int warp = tid >> 5;
    const int wm   = warp >> 1;          // 0..3
    const int wn   = warp & 1;           // 0..1
    const int l4   = lane >> 2;          // 0..7
    const int lc   = lane & 3;           // 0..3
    const int m0   = blockIdx.y * 128;
    const int n0   = blockIdx.x * 64;

    float acc[2][4][4];
#pragma unroll
    for (int mt = 0; mt < 2; mt++)
#pragma unroll
        for (int nt = 0; nt < 4; nt++)
#pragma unroll
            for (int j = 0; j < 4; j++) acc[mt][nt][j] = 0.f;

    const int ar = tid >> 1, ac = (tid & 1) * 16;   // A: 16 floats/thread
    const int br = tid >> 3, bc = (tid & 7) * 8;    // B: 8 floats/thread
    const float* Ap = A + (size_t)(m0 + ar) * K + ac;
    const float* Bp = B + (size_t)br * N + n0 + bc;

    auto stage = [&](int kt, int buf) {
        const float* Aq = Ap + kt * 32;
        const float* Bq = Bp + (size_t)kt * 32 * N;
        uint32_t ad = su + (uint32_t)(buf * G3_A_SZ + ar * AR_STR + ac) * 4;
        uint32_t bd = su + (uint32_t)(2 * G3_A_SZ + buf * G3_B_SZ + br * BR_STR + bc) * 4;
#pragma unroll
        for (int j = 0; j < 4; j++) cp16(ad + 16 * j, Aq + 4 * j);
#pragma unroll
        for (int j = 0; j < 2; j++) cp16(bd + 16 * j, Bq + 4 * j);
        asm volatile("cp.async.commit_group;");
    };

    stage(0, 0);
    const int NT = K / 32;

    for (int kt = 0; kt < NT; kt++) {
        const int cur = kt & 1;
        __syncthreads();   // all warps done computing from buf cur^1
        if (kt + 1 < NT) {
            stage(kt + 1, cur ^ 1);
            asm volatile("cp.async.wait_group 1;");
        } else {
            asm volatile("cp.async.wait_group 0;");
        }
        __syncthreads();

        const float* Ac = Ar + cur * G3_A_SZ;
        const float* Bc = Br + cur * G3_B_SZ;

#pragma unroll
        for (int s = 0; s < 4; s++) {
            const int kk = s * 8 + lc;
            uint32_t ah[2][4], al[2][4];
#pragma unroll
            for (int mt = 0; mt < 2; mt++) {
                int row = wm * 32 + mt * 16 + l4;
                float2 t;
                t = split2t(Ac[(row)     * AR_STR + kk]);     ah[mt][0] = __float_as_uint(t.x); al[mt][0] = __float_as_uint(t.y);
                t = split2t(Ac[(row + 8) * AR_STR + kk]);     ah[mt][1] = __float_as_uint(t.x); al[mt][1] = __float_as_uint(t.y);
                t = split2t(Ac[(row)     * AR_STR + kk + 4]); ah[mt][2] = __float_as_uint(t.x); al[mt][2] = __float_as_uint(t.y);
                t = split2t(Ac[(row + 8) * AR_STR + kk + 4]); ah[mt][3] = __float_as_uint(t.x); al[mt][3] = __float_as_uint(t.y);
            }
#pragma unroll
            for (int nt = 0; nt < 4; nt++) {
                int col = wn * 32 + nt * 8 + l4;
                float2 b0 = split2t(Bc[(kk)     * BR_STR + col]);
                float2 b1 = split2t(Bc[(kk + 4) * BR_STR + col]);
                uint32_t bh0 = __float_as_uint(b0.x), bl0 = __float_as_uint(b0.y);
                uint32_t bh1 = __float_as_uint(b1.x), bl1 = __float_as_uint(b1.y);
#pragma unroll
                for (int mt = 0; mt < 2; mt++) {
                    mma8(acc[mt][nt][0], acc[mt][nt][1], acc[mt][nt][2], acc[mt][nt][3],
                         ah[mt][0], ah[mt][1], ah[mt][2], ah[mt][3], bh0, bh1);
                    mma8(acc[mt][nt][0], acc[mt][nt][1], acc[mt][nt][2], acc[mt][nt][3],
                         ah[mt][0], ah[mt][1], ah[mt][2], ah[mt][3], bl0, bl1);
                    mma8(acc[mt][nt][0], acc[mt][nt][1], acc[mt][nt][2], acc[mt][nt][3],
                         al[mt][0], al[mt][1], al[mt][2], al[mt][3], bh0, bh1);
                }
            }
        }
    }

#pragma unroll
    for (int mt = 0; mt < 2; mt++) {
#pragma unroll
        for (int nt = 0; nt < 4; nt++) {
            int row = m0 + wm * 32 + mt * 16 + l4;
            int col = n0 + wn * 32 + nt * 8 + 2 * lc;
            *(float2*)&C[(size_t)(row)     * N + col] = make_float2(acc[mt][nt][0], acc[mt][nt][1]);
            *(float2*)&C[(size_t)(row + 8) * N + col] = make_float2(acc[mt][nt][2], acc[mt][nt][3]);
        }
    }
}

// ---------------------------------------------------------------------------
// Plain TF32 GEMM (1 MMA per k8), cp.async double-buffered, BK=32.
// V-proj (round_out=1) and O-proj (round_out=0). Pure GEMM launches.
// ---------------------------------------------------------------------------
#define GEMM1_SMEM_BYTES GEMM_SMEM_BYTES

__global__ __launch_bounds__(256, 2) void gemm_tf32_1t(const float* __restrict__ A,
                                                       const float* __restrict__ B,
                                                       float* __restrict__ C,
                                                       int M, int N, int K,
                                                       int round_out)
{
    extern __shared__ float smg[];
    float* Ar = smg;                   // [2][128][AR_STR]
    float* Br = smg + 2 * G3_A_SZ;     // [2][32][BR_STR]
    const uint32_t su = (uint32_t)__cvta_generic_to_shared(smg);

    const int tid  = threadIdx.x;
    const int lane = tid & 31;
    const int warp = tid >> 5;
    const int wm   = warp >> 1;
    const int wn   = warp & 1;
    const int l4   = lane >> 2;
    const int lc   = lane & 3;
    const int m0   = blockIdx.y * 128;
    const int n0   = blockIdx.x * 64;

    float acc[2][4][4];
#pragma unroll
    for (int mt = 0; mt < 2; mt++)
#pragma unroll
        for (int nt = 0; nt < 4; nt++)
#pragma unroll
            for (int j = 0; j < 4; j++) acc[mt][nt][j] = 0.f;

    const int ar = tid >> 1, ac = (tid & 1) * 16;
    const int br = tid >> 3, bc = (tid & 7) * 8;
    const float* Ap = A + (size_t)(m0 + ar) * K + ac;
    const float* Bp = B + (size_t)br * N + n0 + bc;

    auto stage = [&](int kt, int buf) {
        const float* Aq = Ap + kt * 32;
        const float* Bq = Bp + (size_t)kt * 32 * N;
        uint32_t ad = su + (uint32_t)(buf * G3_A_SZ + ar * AR_STR + ac) * 4;
        uint32_t bd = su + (uint32_t)(2 * G3_A_SZ + buf * G3_B_SZ + br * BR_STR + bc) * 4;
#pragma unroll
        for (int j = 0; j < 4; j++) cp16(ad + 16 * j, Aq + 4 * j);
#pragma unroll
        for (int j = 0; j < 2; j++) cp16(bd + 16 * j, Bq + 4 * j);
        asm volatile("cp.async.commit_group;");
    };

    stage(0, 0);
    const int NT = K / 32;

    for (int kt = 0; kt < NT; kt++) {
        const int cur = kt & 1;
        __syncthreads();
        if (kt + 1 < NT) {
            stage(kt + 1, cur ^ 1);
            asm volatile("cp.async.wait_group 1;");
        } else {
            asm volatile("cp.async.wait_group 0;");
        }
        __syncthreads();

        const float* Ac = Ar + cur * G3_A_SZ;
        const float* Bc = Br + cur * G3_B_SZ;

#pragma unroll
        for (int s = 0; s < 4; s++) {
            const int kk = s * 8 + lc;
            uint32_t a[2][4];
#pragma unroll
            for (int mt = 0; mt < 2; mt++) {
                int row = wm * 32 + mt * 16 + l4;
                a[mt][0] = f2tf(Ac[(row)     * AR_STR + kk]);
                a[mt][1] = f2tf(Ac[(row + 8) * AR_STR + kk]);
                a[mt][2] = f2tf(Ac[(row)     * AR_STR + kk + 4]);
                a[mt][3] = f2tf(Ac[(row + 8) * AR_STR + kk + 4]);
            }
#pragma unroll
            for (int nt = 0; nt < 4; nt++) {
                int col = wn * 32 + nt * 8 + l4;
                uint32_t b0 = f2tf(Bc[(kk)     * BR_STR + col]);
                uint32_t b1 = f2tf(Bc[(kk + 4) * BR_STR + col]);
#pragma unroll
                for (int mt = 0; mt < 2; mt++) {
                    mma8(acc[mt][nt][0], acc[mt][nt][1], acc[mt][nt][2], acc[mt][nt][3],
                         a[mt][0], a[mt][1], a[mt][2], a[mt][3], b0, b1);
                }
            }
        }
    }

#pragma unroll
    for (int mt = 0; mt < 2; mt++) {
#pragma unroll
        for (int nt = 0; nt < 4; nt++) {
            int row = m0 + wm * 32 + mt * 16 + l4;
            int col = n0 + wn * 32 + nt * 8 + 2 * lc;
            float v0 = acc[mt][nt][0], v1 = acc[mt][nt][1];
            float v2 = acc[mt][nt][2], v3 = acc[mt][nt][3];
            if (round_out) {
                v0 = __uint_as_float(f2tf(v0)); v1 = __uint_as_float(f2tf(v1));
                v2 = __uint_as_float(f2tf(v2)); v3 = __uint_as_float(f2tf(v3));
            }
            *(float2*)&C[(size_t)(row)     * N + col] = make_float2(v0, v1);
            *(float2*)&C[(size_t)(row + 8) * N + col] = make_float2(v2, v3);
        }
    }
}

// ---------------------------------------------------------------------------
// Flash attention (verified R14 body, unchanged). cp.async double-buffered,
// 2 CTAs/SM, 256 thr, Q-tile 128, K-tile 64, 2-op splits, shuffle P->A frags.
// ---------------------------------------------------------------------------
#define NTILE   (SEQ/64)                 // 32
#define SS_STR  68                        // Qs: [128][68] raw Q (persistent)
#define KR_STR  68                        // Kr: [2][64][68] raw K
#define VR_STR  72                        // Vr: [2][64][72] tf32 V
#define KR_OFF  (128*SS_STR)              // 8704
#define VR_OFF  (KR_OFF + 2*64*KR_STR)    // 17408
#define BW_OFF  (VR_OFF + 2*64*VR_STR)    // 26624
#define MS_OFF  (BW_OFF + 2*192)          // 27008
#define ATTN_SMEM_FLOATS (MS_OFF + 2*64)  // 27136
#define ATTN_SMEM_BYTES  (ATTN_SMEM_FLOATS * 4)   // 108544

__global__ __launch_bounds__(256, 2) void attn_tf32(const float* __restrict__ Q,
                                                    const float* __restrict__ K,
                                                    const float* __restrict__ V,
                                                    const float* __restrict__ mask,
                                                    const float* __restrict__ bias,
                                                    float* __restrict__ O)
{
    extern __shared__ float smf[];
    float* Qs = smf;                    // [128][SS_STR] raw Q, persistent
    float* Kr = smf + KR_OFF;           // [2][64][KR_STR]
    float* Vr = smf + VR_OFF;           // [2][64][VR_STR]
    float* bw = smf + BW_OFF;           // [2][192]
    float* ms = smf + MS_OFF;           // [2][64]
    const uint32_t smem_u = (uint32_t)__cvta_generic_to_shared(smf);

    const int tid  = threadIdx.x;
    const int lane = tid & 31;
    const int warp = tid >> 5;
    const int l4   = lane >> 2;
    const int lc   = lane & 3;
    const int b    = blockIdx.z;
    const int h    = blockIdx.y;
    const int q0   = blockIdx.x * 128;
    const int r0   = warp * 16 + l4;
    const int relbase = h * 4095 + 2047 - q0 - 127;   // + k0 + t

    const int sr = tid >> 2;
    const int sc = (tid & 3) * 16;
    const float* Kst = K + ((size_t)(b * SEQ + sr)) * DIM + h * DKV + sc;
    const float* Vst = V + ((size_t)(b * SEQ + sr)) * DIM + h * DKV + sc;

    auto stage = [&](int k0, int buf) {
        const float* Kb = Kst + (size_t)k0 * DIM;
        const float* Vb = Vst + (size_t)k0 * DIM;
        uint32_t kd = smem_u + (uint32_t)(KR_OFF + buf * 64 * KR_STR + sr * KR_STR + sc) * 4;
        uint32_t vd = smem_u + (uint32_t)(VR_OFF + buf * 64 * VR_STR + sr * VR_STR + sc) * 4;
#pragma unroll
        for (int j = 0; j < 4; j++) {
            cp16(kd + 16 * j, Kb + 4 * j);
            cp16(vd + 16 * j, Vb + 4 * j);
        }
        if (tid < 191) {
            cp4(smem_u + (uint32_t)(BW_OFF + buf * 192 + tid) * 4,
                bias + relbase + k0 + tid);
        } else if (tid >= 192) {
            cp4(smem_u + (uint32_t)(MS_OFF + buf * 64 + tid - 192) * 4,
                mask + b * SEQ + k0 + tid - 192);
        }
        asm volatile("cp.async.commit_group;");
    };

    stage(0, 0);

    {
        int r = tid >> 1, c0 = (tid & 1) * 32;
        const float* Qb = Q + ((size_t)(b * SEQ + q0 + r)) * DIM + h * DKV + c0;
#pragma unroll
        for (int j = 0; j < 8; j++)
            *(float4*)&Qs[r * SS_STR + c0 + 4 * j] = *(const float4*)(Qb + 4 * j);
    }
    __syncthreads();

    const uint32_t qrow0 = smem_u + (uint32_t)((r0)     * SS_STR) * 4;
    const uint32_t qrow8 = smem_u + (uint32_t)((r0 + 8) * SS_STR) * 4;

    float o[8][4];
#pragma unroll
    for (int dt = 0; dt < 8; dt++)
#pragma unroll
        for (int j = 0; j < 4; j++) o[dt][j] = 0.f;
    float mrow[2] = {-INFINITY, -INFINITY};
    float lrow[2] = {0.f, 0.f};

    for (int kt = 0; kt < NTILE; kt++) {
        const int cur = kt & 1;
        __syncthreads();
        if (kt + 1 < NTILE) {
            stage((kt + 1) * 64, cur ^ 1);
            asm volatile("cp.async.wait_group 1;");
        } else {
            asm volatile("cp.async.wait_group 0;");
        }
        __syncthreads();

        const float* Kc  = Kr + cur * 64 * KR_STR;
        const float* bwc = bw + cur * 192;
        const float* msc = ms + cur * 64;

        float sf[8][4];
#pragma unroll
        for (int nt = 0; nt < 8; nt++)
#pragma unroll
            for (int j = 0; j < 4; j++) sf[nt][j] = 0.f;

#pragma unroll
        for (int s = 0; s < 8; s++) {
            const int kk = s * 8 + lc;
            float2 qa0 = split2t(lds32v(qrow0 + (uint32_t)kk * 4));
            float2 qa1 = split2t(lds32v(qrow8 + (uint32_t)kk * 4));
            float2 qa2 = split2t(lds32v(qrow0 + (uint32_t)(kk + 4) * 4));
            float2 qa3 = split2t(lds32v(qrow8 + (uint32_t)(kk + 4) * 4));
            uint32_t qh0 = __float_as_uint(qa0.x), ql0 = __float_as_uint(qa0.y);
            uint32_t qh1 = __float_as_uint(qa1.x), ql1 = __float_as_uint(qa1.y);
            uint32_t qh2 = __float_as_uint(qa2.x), ql2 = __float_as_uint(qa2.y);
            uint32_t qh3 = __float_as_uint(qa3.x), ql3 = __float_as_uint(qa3.y);
#pragma unroll
            for (int nt = 0; nt < 8; nt++) {
                int key = nt * 8 + l4;
                float2 b0 = split2t(Kc[key * KR_STR + kk]);
                float2 b1 = split2t(Kc[key * KR_STR + kk + 4]);
                uint32_t bh0 = __float_as_uint(b0.x), bl0 = __float_as_uint(b0.y);
                uint32_t bh1 = __float_as_uint(b1.x), bl1 = __float_as_uint(b1.y);
                mma8(sf[nt][0], sf[nt][1], sf[nt][2], sf[nt][3],
                     qh0, qh1, qh2, qh3, bh0, bh1);
                mma8(sf[nt][0], sf[nt][1], sf[nt][2], sf[nt][3],
                     qh0, qh1, qh2, qh3, bl0, bl1);
                mma8(sf[nt][0], sf[nt][1], sf[nt][2], sf[nt][3],
                     ql0, ql1, ql2, ql3, bh0, bh1);
            }
        }

#pragma unroll
        for (int i = 0; i < 2; i++) {
            int qlcl = warp * 16 + l4 + 8 * i;
            float vmax = -INFINITY;
#pragma unroll
            for (int nt = 0; nt < 8; nt++) {
#pragma unroll
                for (int j = 0; j < 2; j++) {
                    int klcl = nt * 8 + 2 * lc + j;
                    float v = sf[nt][2 * i + j] + bwc[klcl - qlcl + 127] + msc[klcl];
                    sf[nt][2 * i + j] = v;
                    vmax = fmaxf(vmax, v);
                }
            }
            vmax = fmaxf(vmax, __shfl_xor_sync(0xffffffffu, vmax, 1));
            vmax = fmaxf(vmax, __shfl_xor_sync(0xffffffffu, vmax, 2));
            float mnew = fmaxf(mrow[i], vmax);
            float corr = __expf(mrow[i] - mnew);
            mrow[i] = mnew;
            float rsum = 0.f;
#pragma unroll
            for (int nt = 0; nt < 8; nt++) {
#pragma unroll
                for (int j = 0; j < 2; j++) {
                    float p = __expf(sf[nt][2 * i + j] - mnew);
                    sf[nt][2 * i + j] = p;
                    rsum += p;
                }
            }
            rsum += __shfl_xor_sync(0xffffffffu, rsum, 1);
            rsum += __shfl_xor_sync(0xffffffffu, rsum, 2);
            lrow[i] = lrow[i] * corr + rsum;
#pragma unroll
            for (int dt = 0; dt < 8; dt++) {
                o[dt][2 * i]     *= corr;
                o[dt][2 * i + 1] *= corr;
            }
        }

        const float* Vc = Vr + cur * 64 * VR_STR;
        const int qbase = lane & ~3;
        const int src1  = qbase | (lc >> 1);
        const int src2  = qbase | 2 | (lc >> 1);
        const bool odd  = (lc & 1);
#pragma unroll
        for (int s = 0; s < 8; s++) {
            const int kk = s * 8 + lc;
            float u0 = __shfl_sync(0xffffffffu, sf[s][0], src1);
            float v0 = __shfl_sync(0xffffffffu, sf[s][1], src1);
            float u1 = __shfl_sync(0xffffffffu, sf[s][2], src1);
            float v1 = __shfl_sync(0xffffffffu, sf[s][3], src1);
            float u2 = __shfl_sync(0xffffffffu, sf[s][0], src2);
            float v2 = __shfl_sync(0xffffffffu, sf[s][1], src2);
            float u3 = __shfl_sync(0xffffffffu, sf[s][2], src2);
            float v3 = __shfl_sync(0xffffffffu, sf[s][3], src2);
            uint32_t pa0 = f2tf(odd ? v0 : u0);
            uint32_t pa1 = f2tf(odd ? v1 : u1);
            uint32_t pa2 = f2tf(odd ? v2 : u2);
            uint32_t pa3 = f2tf(odd ? v3 : u3);
#pragma unroll
            for (int dt = 0; dt < 8; dt++) {
                int dc = dt * 8 + l4;
                uint32_t vb0 = __float_as_uint(Vc[(kk)     * VR_STR + dc]);
                uint32_t vb1 = __float_as_uint(Vc[(kk + 4) * VR_STR + dc]);
                mma8(o[dt][0], o[dt][1], o[dt][2], o[dt][3],
                     pa0, pa1, pa2, pa3, vb0, vb1);
            }
        }
    }

#pragma unroll
    for (int i = 0; i < 2; i++) {
        float inv = 1.0f / lrow[i];
        size_t base = ((size_t)(b * SEQ + q0 + warp * 16 + l4 + 8 * i)) * DIM + h * DKV;
#pragma unroll
        for (int dt = 0; dt < 8; dt++) {
            *(float2*)&O[base + dt * 8 + 2 * lc] =
                make_float2(o[dt][2 * i] * inv, o[dt][2 * i + 1] * inv);
        }
    }
}

// ---------------------------------------------------------------------------
// Launch
// ---------------------------------------------------------------------------
extern "C" void kernel_launch(void* const* d_in, const int* in_sizes, int n_in,
                              void* d_out, int out_size)
{
    const float* x         = (const float*)d_in[0];
    const float* Wq        = (const float*)d_in[1];
    const float* Wk        = (const float*)d_in[2];
    const float* Wv        = (const float*)d_in[3];
    const float* Wo        = (const float*)d_in[4];
    const float* rel_table = (const float*)d_in[5];
    const float* mask      = (const float*)d_in[6];
    float* out = (float*)d_out;

    float *pq, *pk, *pv, *pa, *pbias;
    cudaGetSymbolAddress((void**)&pq,    g_q);
    cudaGetSymbolAddress((void**)&pk,    g_k);
    cudaGetSymbolAddress((void**)&pv,    g_v);
    cudaGetSymbolAddress((void**)&pa,    g_attn);
    cudaGetSymbolAddress((void**)&pbias, g_bias_tbl);

    cudaFuncSetAttribute(gemm_tf32, cudaFuncAttributeMaxDynamicSharedMemorySize,
                         GEMM_SMEM_BYTES);
    cudaFuncSetAttribute(gemm_tf32_1t, cudaFuncAttributeMaxDynamicSharedMemorySize,
                         GEMM1_SMEM_BYTES);
    cudaFuncSetAttribute(attn_tf32, cudaFuncAttributeMaxDynamicSharedMemorySize,
                         ATTN_SMEM_BYTES);

    // 1) bias table
    bias_table_kernel<<<(BIAS_TBL_N + 255) / 256, 256>>>(rel_table, pbias);

    // 2) Q,K projections (3-term, fused) + position_bias broadcast (z=2)
    //    pb's DRAM-bound CTAs hide under the long compute-bound QK waves.
    dim3 qkgrid(DIM / 64, MROWS / 128, 3);
    gemm_tf32<<<qkgrid, 256, GEMM_SMEM_BYTES>>>(x, Wq, Wk, pq, pk,
                                                pbias, out + OUT_ELEMS,
                                                MROWS, DIM, DIM);

    // 3) V projection (1-term, output rounded to tf32)
    dim3 vgrid(DIM / 64, MROWS / 128, 1);
    gemm_tf32_1t<<<vgrid, 256, GEMM1_SMEM_BYTES>>>(x, Wv, pv, MROWS, DIM, DIM, 1);

    // 4) flash attention (cp.async pipelined, 2 CTAs/SM, 2-op splits)
    dim3 agrid(SEQ / 128, HEADS, BATCH);
    attn_tf32<<<agrid, 256, ATTN_SMEM_BYTES>>>(pq, pk, pv, mask, pbias, pa);

    // 5) output projection (pure GEMM)
    gemm_tf32_1t<<<vgrid, 256, GEMM1_SMEM_BYTES>>>(pa, Wo, out, MROWS, DIM, DIM, 0);
}

// round 17
// speedup vs baseline: 1.0441x; 1.0032x over previous
#include <cuda_runtime.h>
#include <math.h>
#include <stdint.h>

// Problem constants
#define BATCH 2
#define SEQ   2048
#define DIM   1024
#define HEADS 16
#define DKV   64
#define MROWS (BATCH*SEQ)                          // 4096
#define OUT_ELEMS   ((size_t)MROWS*DIM)            // 4194304
#define PB_ELEMS    ((size_t)HEADS*SEQ*SEQ)        // 67108864
#define BIAS_TBL_N  (HEADS*4095)                   // 65520

// Scratch (device globals, no runtime allocation)
__device__ float g_q[MROWS*DIM];
__device__ float g_k[MROWS*DIM];
__device__ float g_v[MROWS*DIM];
__device__ float g_attn[MROWS*DIM];
__device__ float g_bias_tbl[BIAS_TBL_N];

// ---------------------------------------------------------------------------
// TF32 / cp.async helpers
// ---------------------------------------------------------------------------
__device__ __forceinline__ uint32_t f2tf(float f) {       // RNA round (P/V/1-term)
    uint32_t u;
    asm("cvt.rna.tf32.f32 %0, %1;" : "=r"(u) : "f"(f));
    return u;
}
// 2-op truncating split (verified R14): hi = top-19-bit truncation, lo = f-hi.
__device__ __forceinline__ float2 split2t(float f) {
    float hf = __uint_as_float(__float_as_uint(f) & 0xffffe000u);
    return make_float2(hf, f - hf);
}

__device__ __forceinline__ void mma8(float& d0, float& d1, float& d2, float& d3,
                                     uint32_t a0, uint32_t a1, uint32_t a2, uint32_t a3,
                                     uint32_t b0, uint32_t b1)
{
    asm volatile("mma.sync.aligned.m16n8k8.row.col.f32.tf32.tf32.f32 "
                 "{%0,%1,%2,%3}, {%4,%5,%6,%7}, {%8,%9}, {%0,%1,%2,%3};"
                 : "+f"(d0), "+f"(d1), "+f"(d2), "+f"(d3)
                 : "r"(a0), "r"(a1), "r"(a2), "r"(a3), "r"(b0), "r"(b1));
}

__device__ __forceinline__ void cp16(uint32_t dst, const void* src) {
    asm volatile("cp.async.cg.shared.global [%0], [%1], 16;" :: "r"(dst), "l"(src));
}
__device__ __forceinline__ void cp4(uint32_t dst, const void* src) {
    asm volatile("cp.async.ca.shared.global [%0], [%1], 4;" :: "r"(dst), "l"(src));
}
// volatile shared load (prevents LICM hoisting of loop-invariant Q loads)
__device__ __forceinline__ float lds32v(uint32_t addr) {
    float v;
    asm volatile("ld.shared.f32 %0, [%1];" : "=f"(v) : "r"(addr));
    return v;
}

// ---------------------------------------------------------------------------
// Relative-position bias table: bias[h][rel + 2047], rel = k - q
// ---------------------------------------------------------------------------
__global__ void bias_table_kernel(const float* __restrict__ rel_table,
                                  float* __restrict__ bias)
{
    int i = blockIdx.x * blockDim.x + threadIdx.x;
    if (i >= BIAS_TBL_N) return;
    int h   = i / 4095;
    int rel = (i % 4095) - 2047;       // rel = k - q
    int n   = -rel;                    // q - k
    int ret = 0;
    if (n < 0) { ret = 16; n = -n; }
    int val;
    if (n < 8) {
        val = n;
    } else {
        float t = (logf((float)n / 8.0f) / 2.772588722239781f) * 8.0f;
        int it = (int)t;
        if (t - (float)it > 0.99995f) it += 1;
        val = 8 + it;
        if (val > 15) val = 15;
    }
    bias[i] = rel_table[(val + ret) * HEADS + h];
}

// ---------------------------------------------------------------------------
// Fused QKV projection + pb, cp.async double-buffered, BK=32.
// z==0: Q (3-term)  z==1: K (3-term)  z==2: V (1-term, tf32-rounded store)
// z==3: position_bias broadcast.
// ---------------------------------------------------------------------------
#define AR_STR 36   // floats per A row (128 rows, raw)
#define BR_STR 68   // floats per B row (32 rows, raw)
#define G3_A_SZ (128*AR_STR)
#define G3_B_SZ (32*BR_STR)
#define GEMM_SMEM_BYTES ((2*G3_A_SZ + 2*G3_B_SZ) * 4)   // 54272

__global__ __launch_bounds__(256, 2) void gemm_tf32(const float* __restrict__ A,
                                                    const float* __restrict__ B0,
                                                    const float* __restrict__ B1,
                                                    const float* __restrict__ B2,
                                                    float* __restrict__ C0,
                                                    float* __restrict__ C1,
                                                    float* __restrict__ C2,
                                                    const float* __restrict__ bias_tbl,
                                                    float* __restrict__ pb,
                                                    int M, int N, int K)
{
    const int z = blockIdx.z;
    if (z == 3) {
        // position_bias broadcast: 512 CTAs x 256 thr x 128 iters x float4
        int cta = blockIdx.y * gridDim.x + blockIdx.x;       // 0..511
        size_t base = (size_t)cta * 131072 + threadIdx.x * 4;
#pragma unroll 4
        for (int it = 0; it < 128; it++) {
            size_t i = base + (size_t)it * 1024;
            int k = (int)(i & 2047);
            int q = (int)((i >> 11) & 2047);
            int h = (int)(i >> 22);
            const float* src = bias_tbl + h * 4095 + 2047 - q + k;
            *(float4*)(pb + i) = make_float4(src[0], src[1], src[2], src[3]);
        }
        return;
    }

    const float* B = (z == 0) ? B0 : (z == 1 ? B1 : B2);
    float*       C = (z == 0) ? C0 : (z == 1 ? C1 : C2);

    extern __shared__ float smg[];
    float* Ar = smg;                   // [2][128][AR_STR]
    float* Br = smg + 2 * G3_A_SZ;     // [2][32][BR_STR]
    const uint32_t su = (uint32_t)__cvta_generic_to_shared(smg);

    const int tid  = threadIdx.x;
    const int lane = tid & 31;
    const int warp = tid >> 5;
    const int wm   = warp >> 1;          // 0..3
    const int wn   = warp & 1;           // 0..1
    const int l4   = lane >> 2;          // 0..7
    const int lc   = lane & 3;           // 0..3
    const int m0   = blockIdx.y * 128;
    const int n0   = blockIdx.x * 64;

    float acc[2][4][4];
#pragma unroll
    for (int mt = 0; mt < 2; mt++)
#pragma unroll
        for (int nt = 0; nt < 4; nt++)
#pragma unroll
            for (int j = 0; j < 4; j++) acc[mt][nt][j] = 0.f;

    const int ar = tid >> 1, ac = (tid & 1) * 16;   // A: 16 floats/thread
    const int br = tid >> 3, bc = (tid & 7) * 8;    // B: 8 floats/thread
    const float* Ap = A + (size_t)(m0 + ar) * K + ac;
    const float* Bp = B + (size_t)br * N + n0 + bc;

    auto stage = [&](int kt, int buf) {
        const float* Aq = Ap + kt * 32;
        const float* Bq = Bp + (size_t)kt * 32 * N;
        uint32_t ad = su + (uint32_t)(buf * G3_A_SZ + ar * AR_STR + ac) * 4;
        uint32_t bd = su + (uint32_t)(2 * G3_A_SZ + buf * G3_B_SZ + br * BR_STR + bc) * 4;
#pragma unroll
        for (int j = 0; j < 4; j++) cp16(ad + 16 * j, Aq + 4 * j);
#pragma unroll
        for (int j = 0; j < 2; j++) cp16(bd + 16 * j, Bq + 4 * j);
        asm volatile("cp.async.commit_group;");
    };

    stage(0, 0);
    const int NT = K / 32;

    for (int kt = 0; kt < NT; kt++) {
        const int cur = kt & 1;
        __syncthreads();   // all warps done computing from buf cur^1
        if (kt + 1 < NT) {
            stage(kt + 1, cur ^ 1);
            asm volatile("cp.async.wait_group 1;");
        } else {
            asm volatile("cp.async.wait_group 0;");
        }
        __syncthreads();

        const float* Ac = Ar + cur * G3_A_SZ;
        const float* Bc = Br + cur * G3_B_SZ;

        if (z < 2) {
            // ---- 3-term (split2t) path: Q and K ----
#pragma unroll
            for (int s = 0; s < 4; s++) {
                const int kk = s * 8 + lc;
                uint32_t ah[2][4], al[2][4];
#pragma unroll
                for (int mt = 0; mt < 2; mt++) {
                    int row = wm * 32 + mt * 16 + l4;
                    float2 t;
                    t = split2t(Ac[(row)     * AR_STR + kk]);     ah[mt][0] = __float_as_uint(t.x); al[mt][0] = __float_as_uint(t.y);
                    t = split2t(Ac[(row + 8) * AR_STR + kk]);     ah[mt][1] = __float_as_uint(t.x); al[mt][1] = __float_as_uint(t.y);
                    t = split2t(Ac[(row)     * AR_STR + kk + 4]); ah[mt][2] = __float_as_uint(t.x); al[mt][2] = __float_as_uint(t.y);
                    t = split2t(Ac[(row + 8) * AR_STR + kk + 4]); ah[mt][3] = __float_as_uint(t.x); al[mt][3] = __float_as_uint(t.y);
                }
#pragma unroll
                for (int nt = 0; nt < 4; nt++) {
                    int col = wn * 32 + nt * 8 + l4;
                    float2 b0 = split2t(Bc[(kk)     * BR_STR + col]);
                    float2 b1 = split2t(Bc[(kk + 4) * BR_STR + col]);
                    uint32_t bh0 = __float_as_uint(b0.x), bl0 = __float_as_uint(b0.y);
                    uint32_t bh1 = __float_as_uint(b1.x), bl1 = __float_as_uint(b1.y);
#pragma unroll
                    for (int mt = 0; mt < 2; mt++) {
                        mma8(acc[mt][nt][0], acc[mt][nt][1], acc[mt][nt][2], acc[mt][nt][3],
                             ah[mt][0], ah[mt][1], ah[mt][2], ah[mt][3], bh0, bh1);
                        mma8(acc[mt][nt][0], acc[mt][nt][1], acc[mt][nt][2], acc[mt][nt][3],
                             ah[mt][0], ah[mt][1], ah[mt][2], ah[mt][3], bl0, bl1);
                        mma8(acc[mt][nt][0], acc[mt][nt][1], acc[mt][nt][2], acc[mt][nt][3],
                             al[mt][0], al[mt][1], al[mt][2], al[mt][3], bh0, bh1);
                    }
                }
            }
        } else {
            // ---- 1-term (RNA cvt) path: V ----
#pragma unroll
            for (int s = 0; s < 4; s++) {
                const int kk = s * 8 + lc;
                uint32_t a[2][4];
#pragma unroll
                for (int mt = 0; mt < 2; mt++) {
                    int row = wm * 32 + mt * 16 + l4;
                    a[mt][0] = f2tf(Ac[(row)     * AR_STR + kk]);
                    a[mt][1] = f2tf(Ac[(row + 8) * AR_STR + kk]);
                    a[mt][2] = f2tf(Ac[(row)     * AR_STR + kk + 4]);
                    a[mt][3] = f2tf(Ac[(row + 8) * AR_STR + kk + 4]);
                }
#pragma unroll
                for (int nt = 0; nt < 4; nt++) {
                    int col = wn * 32 + nt * 8 + l4;
                    uint32_t b0 = f2tf(Bc[(kk)     * BR_STR + col]);
                    uint32_t b1 = f2tf(Bc[(kk + 4) * BR_STR + col]);
#pragma unroll
                    for (int mt = 0; mt < 2; mt++) {
                        mma8(acc[mt][nt][0], acc[mt][nt][1], acc[mt][nt][2], acc[mt][nt][3],
                             a[mt][0], a[mt][1], a[mt][2], a[mt][3], b0, b1);
                    }
                }
            }
        }
    }

#pragma unroll
    for (int mt = 0; mt < 2; mt++) {
#pragma unroll
        for (int nt = 0; nt < 4; nt++) {
            int row = m0 + wm * 32 + mt * 16 + l4;
            int col = n0 + wn * 32 + nt * 8 + 2 * lc;
            float v0 = acc[mt][nt][0], v1 = acc[mt][nt][1];
            float v2 = acc[mt][nt][2], v3 = acc[mt][nt][3];
            if (z == 2) {   // V: pre-round to tf32 for the attention PV stage
                v0 = __uint_as_float(f2tf(v0)); v1 = __uint_as_float(f2tf(v1));
                v2 = __uint_as_float(f2tf(v2)); v3 = __uint_as_float(f2tf(v3));
            }
            *(float2*)&C[(size_t)(row)     * N + col] = make_float2(v0, v1);
            *(float2*)&C[(size_t)(row + 8) * N + col] = make_float2(v2, v3);
        }
    }
}

// ---------------------------------------------------------------------------
// 1-term TF32 GEMM, BK=64 (O-projection). Staging geometry verified in R15.
// ---------------------------------------------------------------------------
#define O_AR_STR 68   // floats per A row (128 rows)
#define O_BR_STR 68   // floats per B row (64 rows)
#define O_A_SZ (128*O_AR_STR)    // 8704
#define O_B_SZ (64*O_BR_STR)     // 4352
#define GEMMO_SMEM_BYTES ((2*O_A_SZ + 2*O_B_SZ) * 4)   // 104448

__global__ __launch_bounds__(256, 2) void gemm_o64(const float* __restrict__ A,
                                                   const float* __restrict__ B,
                                                   float* __restrict__ C,
                                                   int M, int N, int K)
{
    extern __shared__ float smg[];
    float* Ar = smg;                   // [2][128][O_AR_STR]
    float* Br = smg + 2 * O_A_SZ;      // [2][64][O_BR_STR]
    const uint32_t su = (uint32_t)__cvta_generic_to_shared(smg);

    const int tid  = threadIdx.x;
    const int lane = tid & 31;
    const int warp = tid >> 5;
    const int wm   = warp >> 1;
    const int wn   = warp & 1;
    const int l4   = lane >> 2;
    const int lc   = lane & 3;
    const int m0   = blockIdx.y * 128;
    const int n0   = blockIdx.x * 64;

    float acc[2][4][4];
#pragma unroll
    for (int mt = 0; mt < 2; mt++)
#pragma unroll
        for (int nt = 0; nt < 4; nt++)
#pragma unroll
            for (int j = 0; j < 4; j++) acc[mt][nt][j] = 0.f;

    // staging: A 128x64 (32 floats/thread), B 64x64 (16 floats/thread)
    const int ar = tid >> 1, ac = (tid & 1) * 32;
    const int br = tid >> 2, bc = (tid & 3) * 16;
    const float* Ap = A + (size_t)(m0 + ar) * K + ac;
    const float* Bp = B + (size_t)br * N + n0 + bc;

    auto stage = [&](int kt, int buf) {
        const float* Aq = Ap + kt * 64;
        const float* Bq = Bp + (size_t)kt * 64 * N;
        uint32_t ad = su + (uint32_t)(buf * O_A_SZ + ar * O_AR_STR + ac) * 4;
        uint32_t bd = su + (uint32_t)(2 * O_A_SZ + buf * O_B_SZ + br * O_BR_STR + bc) * 4;
#pragma unroll
        for (int j = 0; j < 8; j++) cp16(ad + 16 * j, Aq + 4 * j);
#pragma unroll
        for (int j = 0; j < 4; j++) cp16(bd + 16 * j, Bq + 4 * j);
        asm volatile("cp.async.commit_group;");
    };

    stage(0, 0);
    const int NT = K / 64;   // 16

    for (int kt = 0; kt < NT; kt++) {
        const int cur = kt & 1;
        __syncthreads();
        if (kt + 1 < NT) {
            stage(kt + 1, cur ^ 1);
            asm volatile("cp.async.wait_group 1;");
        } else {
            asm volatile("cp.async.wait_group 0;");
        }
        __syncthreads();

        const float* Ac = Ar + cur * O_A_SZ;
        const float* Bc = Br + cur * O_B_SZ;

#pragma unroll
        for (int s = 0; s < 8; s++) {
            const int kk = s * 8 + lc;
            uint32_t a[2][4];
#pragma unroll
            for (int mt = 0; mt < 2; mt++) {
                int row = wm * 32 + mt * 16 + l4;
                a[mt][0] = f2tf(Ac[(row)     * O_AR_STR + kk]);
                a[mt][1] = f2tf(Ac[(row + 8) * O_AR_STR + kk]);
                a[mt][2] = f2tf(Ac[(row)     * O_AR_STR + kk + 4]);
                a[mt][3] = f2tf(Ac[(row + 8) * O_AR_STR + kk + 4]);
            }
#pragma unroll
            for (int nt = 0; nt < 4; nt++) {
                int col = wn * 32 + nt * 8 + l4;
                uint32_t b0 = f2tf(Bc[(kk)     * O_BR_STR + col]);
                uint32_t b1 = f2tf(Bc[(kk + 4) * O_BR_STR + col]);
#pragma unroll
                for (int mt = 0; mt < 2; mt++) {
                    mma8(acc[mt][nt][0], acc[mt][nt][1], acc[mt][nt][2], acc[mt][nt][3],
                         a[mt][0], a[mt][1], a[mt][2], a[mt][3], b0, b1);
                }
            }
        }
    }

#pragma unroll
    for (int mt = 0; mt < 2; mt++) {
#pragma unroll
        for (int nt = 0; nt < 4; nt++) {
            int row = m0 + wm * 32 + mt * 16 + l4;
            int col = n0 + wn * 32 + nt * 8 + 2 * lc;
            *(float2*)&C[(size_t)(row)     * N + col] = make_float2(acc[mt][nt][0], acc[mt][nt][1]);
            *(float2*)&C[(size_t)(row + 8) * N + col] = make_float2(acc[mt][nt][2], acc[mt][nt][3]);
        }
    }
}

// ---------------------------------------------------------------------------
// Flash attention (verified R14 body, unchanged). cp.async double-buffered,
// 2 CTAs/SM, 256 thr, Q-tile 128, K-tile 64, 2-op splits, shuffle P->A frags.
// ---------------------------------------------------------------------------
#define NTILE   (SEQ/64)                 // 32
#define SS_STR  68                        // Qs: [128][68] raw Q (persistent)
#define KR_STR  68                        // Kr: [2][64][68] raw K
#define VR_STR  72                        // Vr: [2][64][72] tf32 V
#define KR_OFF  (128*SS_STR)              // 8704
#define VR_OFF  (KR_OFF + 2*64*KR_STR)    // 17408
#define BW_OFF  (VR_OFF + 2*64*VR_STR)    // 26624
#define MS_OFF  (BW_OFF + 2*192)          // 27008
#define ATTN_SMEM_FLOATS (MS_OFF + 2*64)  // 27136
#define ATTN_SMEM_BYTES  (ATTN_SMEM_FLOATS * 4)   // 108544

__global__ __launch_bounds__(256, 2) void attn_tf32(const float* __restrict__ Q,
                                                    const float* __restrict__ K,
                                                    const float* __restrict__ V,
                                                    const float* __restrict__ mask,
                                                    const float* __restrict__ bias,
                                                    float* __restrict__ O)
{
    extern __shared__ float smf[];
    float* Qs = smf;                    // [128][SS_STR] raw Q, persistent
    float* Kr = smf + KR_OFF;           // [2][64][KR_STR]
    float* Vr = smf + VR_OFF;           // [2][64][VR_STR]
    float* bw = smf + BW_OFF;           // [2][192]
    float* ms = smf + MS_OFF;           // [2][64]
    const uint32_t smem_u = (uint32_t)__cvta_generic_to_shared(smf);

    const int tid  = threadIdx.x;
    const int lane = tid & 31;
    const int warp = tid >> 5;
    const int l4   = lane >> 2;
    const int lc   = lane & 3;
    const int b    = blockIdx.z;
    const int h    = blockIdx.y;
    const int q0   = blockIdx.x * 128;
    const int r0   = warp * 16 + l4;
    const int relbase = h * 4095 + 2047 - q0 - 127;   // + k0 + t

    const int sr = tid >> 2;
    const int sc = (tid & 3) * 16;
    const float* Kst = K + ((size_t)(b * SEQ + sr)) * DIM + h * DKV + sc;
    const float* Vst = V + ((size_t)(b * SEQ + sr)) * DIM + h * DKV + sc;

    auto stage = [&](int k0, int buf) {
        const float* Kb = Kst + (size_t)k0 * DIM;
        const float* Vb = Vst + (size_t)k0 * DIM;
        uint32_t kd = smem_u + (uint32_t)(KR_OFF + buf * 64 * KR_STR + sr * KR_STR + sc) * 4;
        uint32_t vd = smem_u + (uint32_t)(VR_OFF + buf * 64 * VR_STR + sr * VR_STR + sc) * 4;
#pragma unroll
        for (int j = 0; j < 4; j++) {
            cp16(kd + 16 * j, Kb + 4 * j);
            cp16(vd + 16 * j, Vb + 4 * j);
        }
        if (tid < 191) {
            cp4(smem_u + (uint32_t)(BW_OFF + buf * 192 + tid) * 4,
                bias + relbase + k0 + tid);
        } else if (tid >= 192) {
            cp4(smem_u + (uint32_t)(MS_OFF + buf * 64 + tid - 192) * 4,
                mask + b * SEQ + k0 + tid - 192);
        }
        asm volatile("cp.async.commit_group;");
    };

    stage(0, 0);

    {
        int r = tid >> 1, c0 = (tid & 1) * 32;
        const float* Qb = Q + ((size_t)(b * SEQ + q0 + r)) * DIM + h * DKV + c0;
#pragma unroll
        for (int j = 0; j < 8; j++)
            *(float4*)&Qs[r * SS_STR + c0 + 4 * j] = *(const float4*)(Qb + 4 * j);
    }
    __syncthreads();

    const uint32_t qrow0 = smem_u + (uint32_t)((r0)     * SS_STR) * 4;
    const uint32_t qrow8 = smem_u + (uint32_t)((r0 + 8) * SS_STR) * 4;

    float o[8][4];
#pragma unroll
    for (int dt = 0; dt < 8; dt++)
#pragma unroll
        for (int j = 0; j < 4; j++) o[dt][j] = 0.f;
    float mrow[2] = {-INFINITY, -INFINITY};
    float lrow[2] = {0.f, 0.f};

    for (int kt = 0; kt < NTILE; kt++) {
        const int cur = kt & 1;
        __syncthreads();
        if (kt + 1 < NTILE) {
            stage((kt + 1) * 64, cur ^ 1);
            asm volatile("cp.async.wait_group 1;");
        } else {
            asm volatile("cp.async.wait_group 0;");
        }
        __syncthreads();

        const float* Kc  = Kr + cur * 64 * KR_STR;
        const float* bwc = bw + cur * 192;
        const float* msc = ms + cur * 64;

        float sf[8][4];
#pragma unroll
        for (int nt = 0; nt < 8; nt++)
#pragma unroll
            for (int j = 0; j < 4; j++) sf[nt][j] = 0.f;

#pragma unroll
        for (int s = 0; s < 8; s++) {
            const int kk = s * 8 + lc;
            float2 qa0 = split2t(lds32v(qrow0 + (uint32_t)kk * 4));
            float2 qa1 = split2t(lds32v(qrow8 + (uint32_t)kk * 4));
            float2 qa2 = split2t(lds32v(qrow0 + (uint32_t)(kk + 4) * 4));
            float2 qa3 = split2t(lds32v(qrow8 + (uint32_t)(kk + 4) * 4));
            uint32_t qh0 = __float_as_uint(qa0.x), ql0 = __float_as_uint(qa0.y);
            uint32_t qh1 = __float_as_uint(qa1.x), ql1 = __float_as_uint(qa1.y);
            uint32_t qh2 = __float_as_uint(qa2.x), ql2 = __float_as_uint(qa2.y);
            uint32_t qh3 = __float_as_uint(qa3.x), ql3 = __float_as_uint(qa3.y);
#pragma unroll
            for (int nt = 0; nt < 8; nt++) {
                int key = nt * 8 + l4;
                float2 b0 = split2t(Kc[key * KR_STR + kk]);
                float2 b1 = split2t(Kc[key * KR_STR + kk + 4]);
                uint32_t bh0 = __float_as_uint(b0.x), bl0 = __float_as_uint(b0.y);
                uint32_t bh1 = __float_as_uint(b1.x), bl1 = __float_as_uint(b1.y);
                mma8(sf[nt][0], sf[nt][1], sf[nt][2], sf[nt][3],
                     qh0, qh1, qh2, qh3, bh0, bh1);
                mma8(sf[nt][0], sf[nt][1], sf[nt][2], sf[nt][3],
                     qh0, qh1, qh2, qh3, bl0, bl1);
                mma8(sf[nt][0], sf[nt][1], sf[nt][2], sf[nt][3],
                     ql0, ql1, ql2, ql3, bh0, bh1);
            }
        }

#pragma unroll
        for (int i = 0; i < 2; i++) {
            int qlcl = warp * 16 + l4 + 8 * i;
            float vmax = -INFINITY;
#pragma unroll
            for (int nt = 0; nt < 8; nt++) {
#pragma unroll
                for (int j = 0; j < 2; j++) {
                    int klcl = nt * 8 + 2 * lc + j;
                    float v = sf[nt][2 * i + j] + bwc[klcl - qlcl + 127] + msc[klcl];
                    sf[nt][2 * i + j] = v;
                    vmax = fmaxf(vmax, v);
                }
            }
            vmax = fmaxf(vmax, __shfl_xor_sync(0xffffffffu, vmax, 1));
            vmax = fmaxf(vmax, __shfl_xor_sync(0xffffffffu, vmax, 2));
            float mnew = fmaxf(mrow[i], vmax);
            float corr = __expf(mrow[i] - mnew);
            mrow[i] = mnew;
            float rsum = 0.f;
#pragma unroll
            for (int nt = 0; nt < 8; nt++) {
#pragma unroll
                for (int j = 0; j < 2; j++) {
                    float p = __expf(sf[nt][2 * i + j] - mnew);
                    sf[nt][2 * i + j] = p;
                    rsum += p;
                }
            }
            rsum += __shfl_xor_sync(0xffffffffu, rsum, 1);
            rsum += __shfl_xor_sync(0xffffffffu, rsum, 2);
            lrow[i] = lrow[i] * corr + rsum;
#pragma unroll
            for (int dt = 0; dt < 8; dt++) {
                o[dt][2 * i]     *= corr;
                o[dt][2 * i + 1] *= corr;
            }
        }

        const float* Vc = Vr + cur * 64 * VR_STR;
        const int qbase = lane & ~3;
        const int src1  = qbase | (lc >> 1);
        const int src2  = qbase | 2 | (lc >> 1);
        const bool odd  = (lc & 1);
#pragma unroll
        for (int s = 0; s < 8; s++) {
            const int kk = s * 8 + lc;
            float u0 = __shfl_sync(0xffffffffu, sf[s][0], src1);
            float v0 = __shfl_sync(0xffffffffu, sf[s][1], src1);
            float u1 = __shfl_sync(0xffffffffu, sf[s][2], src1);
            float v1 = __shfl_sync(0xffffffffu, sf[s][3], src1);
            float u2 = __shfl_sync(0xffffffffu, sf[s][0], src2);
            float v2 = __shfl_sync(0xffffffffu, sf[s][1], src2);
            float u3 = __shfl_sync(0xffffffffu, sf[s][2], src2);
            float v3 = __shfl_sync(0xffffffffu, sf[s][3], src2);
            uint32_t pa0 = f2tf(odd ? v0 : u0);
            uint32_t pa1 = f2tf(odd ? v1 : u1);
            uint32_t pa2 = f2tf(odd ? v2 : u2);
            uint32_t pa3 = f2tf(odd ? v3 : u3);
#pragma unroll
            for (int dt = 0; dt < 8; dt++) {
                int dc = dt * 8 + l4;
                uint32_t vb0 = __float_as_uint(Vc[(kk)     * VR_STR + dc]);
                uint32_t vb1 = __float_as_uint(Vc[(kk + 4) * VR_STR + dc]);
                mma8(o[dt][0], o[dt][1], o[dt][2], o[dt][3],
                     pa0, pa1, pa2, pa3, vb0, vb1);
            }
        }
    }

#pragma unroll
    for (int i = 0; i < 2; i++) {
        float inv = 1.0f / lrow[i];
        size_t base = ((size_t)(b * SEQ + q0 + warp * 16 + l4 + 8 * i)) * DIM + h * DKV;
#pragma unroll
        for (int dt = 0; dt < 8; dt++) {
            *(float2*)&O[base + dt * 8 + 2 * lc] =
                make_float2(o[dt][2 * i] * inv, o[dt][2 * i + 1] * inv);
        }
    }
}

// ---------------------------------------------------------------------------
// Launch
// ---------------------------------------------------------------------------
extern "C" void kernel_launch(void* const* d_in, const int* in_sizes, int n_in,
                              void* d_out, int out_size)
{
    const float* x         = (const float*)d_in[0];
    const float* Wq        = (const float*)d_in[1];
    const float* Wk        = (const float*)d_in[2];
    const float* Wv        = (const float*)d_in[3];
    const float* Wo        = (const float*)d_in[4];
    const float* rel_table = (const float*)d_in[5];
    const float* mask      = (const float*)d_in[6];
    float* out = (float*)d_out;

    float *pq, *pk, *pv, *pa, *pbias;
    cudaGetSymbolAddress((void**)&pq,    g_q);
    cudaGetSymbolAddress((void**)&pk,    g_k);
    cudaGetSymbolAddress((void**)&pv,    g_v);
    cudaGetSymbolAddress((void**)&pa,    g_attn);
    cudaGetSymbolAddress((void**)&pbias, g_bias_tbl);

    cudaFuncSetAttribute(gemm_tf32, cudaFuncAttributeMaxDynamicSharedMemorySize,
                         GEMM_SMEM_BYTES);
    cudaFuncSetAttribute(gemm_o64, cudaFuncAttributeMaxDynamicSharedMemorySize,
                         GEMMO_SMEM_BYTES);
    cudaFuncSetAttribute(attn_tf32, cudaFuncAttributeMaxDynamicSharedMemorySize,
                         ATTN_SMEM_BYTES);

    // 1) bias table
    bias_table_kernel<<<(BIAS_TBL_N + 255) / 256, 256>>>(rel_table, pbias);

    // 2) fused Q,K (3-term) + V (1-term) projections + pb broadcast (z=3)
    dim3 qkvgrid(DIM / 64, MROWS / 128, 4);
    gemm_tf32<<<qkvgrid, 256, GEMM_SMEM_BYTES>>>(x, Wq, Wk, Wv, pq, pk, pv,
                                                 pbias, out + OUT_ELEMS,
                                                 MROWS, DIM, DIM);

    // 3) flash attention (cp.async pipelined, 2 CTAs/SM, 2-op splits)
    dim3 agrid(SEQ / 128, HEADS, BATCH);
    attn_tf32<<<agrid, 256, ATTN_SMEM_BYTES>>>(pq, pk, pv, mask, pbias, pa);

    // 4) output projection (1-term, BK=64)
    dim3 ogrid(DIM / 64, MROWS / 128);
    gemm_o64<<<ogrid, 256, GEMMO_SMEM_BYTES>>>(pa, Wo, out, MROWS, DIM, DIM);
}